// round 15
// baseline (speedup 1.0000x reference)
#include <cuda_runtime.h>
#include <math.h>

#define B_   8
#define C_   192
#define TX_  512
#define TY_  2048
#define NEG_INF_F (-1e9f)

#define PATH_SZ ((size_t)B_*TY_*TX_)            /* 8388608 */
#define GATH_SZ ((size_t)B_*C_*TY_)             /* 3145728 */
#define MPA_OFF  (PATH_SZ)
#define LPA_OFF  (PATH_SZ + GATH_SZ)
#define LOSS_OFF (PATH_SZ + 2*GATH_SZ)
#define DUR_OFF  (LOSS_OFF + 1)

#define KL_BLOCKS (B_*C_*(TY_/256))             /* 12288 */
/* smem: dirs (TY*32 ushort) | dur (TX int) | idx (TY int) | row ring 8*512 f32 */
#define SM_DUR  ((size_t)TY_*32*2)              /* 131072 */
#define SM_IDX  (SM_DUR + TX_*4)                /* 133120 */
#define SM_RING (SM_IDX + TY_*4)                /* 141312 */
#define DP_SMEM (SM_RING + 8*512*4)             /* 157696 */

// ---------------- scratch (__device__ globals; no runtime allocation) -------
__device__ float g_s [B_*C_*TX_];               // -0.5 * exp(-2*logs_p)
__device__ float g_ms[B_*C_*TX_];               // m_p * exp(-2*logs_p)
__device__ float g_nc14[B_*TX_];                // nc1 + nc4
__device__ float g_negcent[(size_t)B_*TY_*TX_]; // rows >= spec_len stay 0 (never written)
__device__ int   g_idx[B_*TY_];                 // backtrack path index, -1 inactive
__device__ int   g_speclen[B_];                 // written by k_prep_b (pre-negcent)
__device__ float g_klpart[KL_BLOCKS];

// ---------------- packed fp32x2 helpers (sm_100+) ----------------------------
__device__ __forceinline__ unsigned long long ffma2(unsigned long long a,
                                                    unsigned long long b,
                                                    unsigned long long c) {
    unsigned long long d;
    asm("fma.rn.f32x2 %0, %1, %2, %3;" : "=l"(d) : "l"(a), "l"(b), "l"(c));
    return d;
}
__device__ __forceinline__ unsigned long long dup2(float f) {
    unsigned long long d;
    unsigned r = __float_as_uint(f);
    asm("mov.b64 %0, {%1, %1};" : "=l"(d) : "r"(r));
    return d;
}
__device__ __forceinline__ void unpk2(unsigned long long v, float& lo, float& hi) {
    unsigned a, b;
    asm("mov.b64 {%0, %1}, %2;" : "=r"(a), "=r"(b) : "l"(v));
    lo = __uint_as_float(a);
    hi = __uint_as_float(b);
}

// ---------------- cp.async helpers -------------------------------------------
__device__ __forceinline__ void cp16(const void* smem_ptr, const void* gptr) {
    unsigned sa = (unsigned)__cvta_generic_to_shared(smem_ptr);
    asm volatile("cp.async.cg.shared.global [%0], [%1], 16;" :: "r"(sa), "l"(gptr));
}
#define CP_COMMIT() asm volatile("cp.async.commit_group;")
#define CP_WAIT0()  asm volatile("cp.async.wait_group 0;")
#define CP_WAIT7()  asm volatile("cp.async.wait_group 7;")

// ---------------- profiler-steering no-op ------------------------------------
__global__ void k_nop() {}

// ---------------- prep: s' = -0.5*s, ms, nc14, spec_len ----------------------
__global__ void k_prep_b(const float* __restrict__ m_p,
                         const float* __restrict__ logs_p,
                         const float* __restrict__ spec_mask) {
    int x  = blockIdx.x * 32 + threadIdx.x;
    int b  = blockIdx.y;
    int ty = threadIdx.y;

    if (blockIdx.x == 0 && ty == 2) {
        float ss = 0.f;
        for (int i = threadIdx.x; i < TY_; i += 32) ss += spec_mask[b*TY_ + i];
        #pragma unroll
        for (int o = 16; o > 0; o >>= 1) ss += __shfl_xor_sync(0xffffffffu, ss, o);
        if (threadIdx.x == 0) g_speclen[b] = (int)rintf(ss);
    }

    float part = 0.f;
    for (int c = ty; c < C_; c += 8) {
        int off = (b*C_ + c)*TX_ + x;
        float lp = logs_p[off];
        float m  = m_p[off];
        float s  = expf(-2.f * lp);
        float ms = m * s;
        g_s[off]  = -0.5f * s;
        g_ms[off] = ms;
        part += (-0.91893853320467274178f - lp - 0.5f*m*ms);
    }
    __shared__ float red[8][32];
    red[ty][threadIdx.x] = part;
    __syncthreads();
    if (ty == 0) {
        float t = 0.f;
        #pragma unroll
        for (int r = 0; r < 8; ++r) t += red[r][threadIdx.x];
        g_nc14[b*TX_ + x] = t;
    }
}

// ---------------- neg_cent GEMM: acc += z*(z*(-0.5s) + ms) -------------------
#define BM 128
#define BN 128

__global__ void __launch_bounds__(256) k_negcent(const float* __restrict__ z_p) {
    int b  = blockIdx.z;
    int t0 = blockIdx.y * BM;
    if (t0 >= g_speclen[b]) return;   // dead rows: nothing downstream reads them

    __shared__ __align__(16) float Zs[2][8][BM];
    __shared__ __align__(16) float Ss[2][8][BN];
    __shared__ __align__(16) float Ms[2][8][BN];

    int tid = threadIdx.x;
    int tx = tid & 15, ty = tid >> 4;
    int x0 = blockIdx.x * BN;

    int lk = tid >> 5;
    int lc = (tid & 31) * 4;

    const float* zb  = z_p  + (size_t)b*C_*TY_ + t0;
    const float* sb  = g_s  + b*C_*TX_ + x0;
    const float* msb = g_ms + b*C_*TX_ + x0;

    unsigned long long acc[8][4];
    #pragma unroll
    for (int i = 0; i < 8; ++i)
        #pragma unroll
        for (int j = 0; j < 4; ++j) acc[i][j] = 0ull;

    cp16(&Zs[0][lk][lc], zb  + (size_t)lk*TY_ + lc);
    cp16(&Ss[0][lk][lc], sb  + lk*TX_ + lc);
    cp16(&Ms[0][lk][lc], msb + lk*TX_ + lc);
    CP_COMMIT();

    int buf = 0;
    for (int c0 = 0; c0 < C_; c0 += 8) {
        CP_WAIT0();
        __syncthreads();
        if (c0 + 8 < C_) {
            int nb = buf ^ 1, ck = c0 + 8;
            cp16(&Zs[nb][lk][lc], zb  + (size_t)(ck+lk)*TY_ + lc);
            cp16(&Ss[nb][lk][lc], sb  + (ck+lk)*TX_ + lc);
            cp16(&Ms[nb][lk][lc], msb + (ck+lk)*TX_ + lc);
            CP_COMMIT();
        }

        #pragma unroll
        for (int k = 0; k < 8; ++k) {
            float4 zA = *(const float4*)&Zs[buf][k][ty*8];
            float4 zB = *(const float4*)&Zs[buf][k][ty*8+4];
            unsigned long long zd[8] = {dup2(zA.x), dup2(zA.y), dup2(zA.z), dup2(zA.w),
                                        dup2(zB.x), dup2(zB.y), dup2(zB.z), dup2(zB.w)};
            ulonglong2 sA = *(const ulonglong2*)&Ss[buf][k][tx*8];
            ulonglong2 sB = *(const ulonglong2*)&Ss[buf][k][tx*8+4];
            ulonglong2 mA = *(const ulonglong2*)&Ms[buf][k][tx*8];
            ulonglong2 mB = *(const ulonglong2*)&Ms[buf][k][tx*8+4];
            unsigned long long sp[4] = {sA.x, sA.y, sB.x, sB.y};
            unsigned long long mp[4] = {mA.x, mA.y, mB.x, mB.y};

            #pragma unroll
            for (int i = 0; i < 8; ++i)
                #pragma unroll
                for (int j = 0; j < 4; ++j)
                    acc[i][j] = ffma2(zd[i], ffma2(zd[i], sp[j], mp[j]), acc[i][j]);
        }
        buf ^= 1;
    }

    int xo = x0 + tx*8;
    float4 ncA = *(const float4*)(g_nc14 + b*TX_ + xo);
    float4 ncB = *(const float4*)(g_nc14 + b*TX_ + xo + 4);
    float nc[8] = {ncA.x, ncA.y, ncA.z, ncA.w, ncB.x, ncB.y, ncB.z, ncB.w};

    #pragma unroll
    for (int i = 0; i < 8; ++i) {
        float f[8];
        #pragma unroll
        for (int j = 0; j < 4; ++j) unpk2(acc[i][j], f[2*j], f[2*j+1]);
        int t = t0 + ty*8 + i;
        float* o0 = g_negcent + ((size_t)b*TY_ + t)*TX_ + xo;
        float4 w;
        w.x = f[0]+nc[0]; w.y = f[1]+nc[1]; w.z = f[2]+nc[2]; w.w = f[3]+nc[3];
        *(float4*)o0 = w;
        w.x = f[4]+nc[4]; w.y = f[5]+nc[5]; w.z = f[6]+nc[6]; w.w = f[7]+nc[7];
        *(float4*)(o0+4) = w;
    }
}

// ---------------- MAS forward DP + backtrack (pipelined LDS + cp.async ring) --
// Lane L owns x = q*128 + L*4 + j  (q=0..3, j=0..3).
// Dirs mask bit for x: lane=(x>>2)&31, bit=((x>>7)<<2)|(x&3).
// Per-q mask nibbles (independent OR chains) merged before the STS.
// ALL inner-loop bounds compile-time (R8 lesson).

#define DP_Q(Q, DB, RQ, MM) do {                                              \
    float sc0 = RQ.x, sc1 = RQ.y, sc2 = RQ.z, sc3 = RQ.w;                     \
    { bool p = v[Q][2] > v[Q][3]; if (p) MM |= (1u << (Q*4+3));               \
      v[Q][3] = sc3 + (p ? v[Q][2] : v[Q][3]); }                              \
    { bool p = v[Q][1] > v[Q][2]; if (p) MM |= (1u << (Q*4+2));               \
      v[Q][2] = sc2 + (p ? v[Q][1] : v[Q][2]); }                              \
    { bool p = v[Q][0] > v[Q][1]; if (p) MM |= (1u << (Q*4+1));               \
      v[Q][1] = sc1 + (p ? v[Q][0] : v[Q][1]); }                              \
    { bool p = (DB) > v[Q][0];    if (p) MM |= (1u << (Q*4+0));               \
      v[Q][0] = sc0 + (p ? (DB) : v[Q][0]); }                                 \
} while (0)

/* stage: commit row yy+8 (dummy=row TY-1 at tail), wait, LDS row yy+1 -> regs */
#define DP_STAGE(SLOT, yy) do {                                               \
    const float* rp = base +                                                  \
        (size_t)(((yy)+8 < TY_) ? (yy)+8 : TY_-1)*TX_;                        \
    float* sd = srow + (SLOT)*512;                                            \
    cp16(sd,       rp);                                                       \
    cp16(sd + 128, rp + 128);                                                 \
    cp16(sd + 256, rp + 256);                                                 \
    cp16(sd + 384, rp + 384);                                                 \
    CP_COMMIT();                                                              \
    CP_WAIT7();                                                               \
    { const float* sl = srow + ((((yy)+1)&7))*512;                            \
      float4* nb = cbuf[((yy)+1)&1];                                          \
      nb[0] = *(const float4*)(sl);                                           \
      nb[1] = *(const float4*)(sl + 128);                                     \
      nb[2] = *(const float4*)(sl + 256);                                     \
      nb[3] = *(const float4*)(sl + 384); }                                   \
} while (0)

#define DP_ROW1(SLOT, yy) do {                                                \
    DP_STAGE(SLOT, yy);                                                       \
    float4 r0 = cbuf[(yy)&1][0];                                              \
    unsigned m0 = 0;                                                          \
    float b0 = __shfl_sync(0xffffffffu, v[0][3], (lane+31)&31);               \
    float d0 = lane0 ? NEG_INF_F : b0;                                        \
    DP_Q(0, d0, r0, m0);                                                      \
    sdirs[(yy)*32 + lane] = (unsigned short)m0;                               \
} while (0)

#define DP_ROW2(SLOT, yy) do {                                                \
    DP_STAGE(SLOT, yy);                                                       \
    float4 r0 = cbuf[(yy)&1][0], r1 = cbuf[(yy)&1][1];                        \
    unsigned m0 = 0, m1 = 0;                                                  \
    float b0 = __shfl_sync(0xffffffffu, v[0][3], (lane+31)&31);               \
    float b1 = __shfl_sync(0xffffffffu, v[1][3], (lane+31)&31);               \
    float d0 = lane0 ? NEG_INF_F : b0;                                        \
    float d1 = lane0 ? b0 : b1;                                               \
    DP_Q(0, d0, r0, m0); DP_Q(1, d1, r1, m1);                                 \
    sdirs[(yy)*32 + lane] = (unsigned short)(m0 | m1);                        \
} while (0)

#define DP_ROW3(SLOT, yy) do {                                                \
    DP_STAGE(SLOT, yy);                                                       \
    float4 r0 = cbuf[(yy)&1][0], r1 = cbuf[(yy)&1][1], r2 = cbuf[(yy)&1][2];  \
    unsigned m0 = 0, m1 = 0, m2 = 0;                                          \
    float b0 = __shfl_sync(0xffffffffu, v[0][3], (lane+31)&31);               \
    float b1 = __shfl_sync(0xffffffffu, v[1][3], (lane+31)&31);               \
    float b2 = __shfl_sync(0xffffffffu, v[2][3], (lane+31)&31);               \
    float d0 = lane0 ? NEG_INF_F : b0;                                        \
    float d1 = lane0 ? b0 : b1;                                               \
    float d2 = lane0 ? b1 : b2;                                               \
    DP_Q(0, d0, r0, m0); DP_Q(1, d1, r1, m1); DP_Q(2, d2, r2, m2);            \
    sdirs[(yy)*32 + lane] = (unsigned short)((m0 | m1) | m2);                 \
} while (0)

#define DP_ROW4(SLOT, yy) do {                                                \
    DP_STAGE(SLOT, yy);                                                       \
    float4 r0 = cbuf[(yy)&1][0], r1 = cbuf[(yy)&1][1];                        \
    float4 r2 = cbuf[(yy)&1][2], r3 = cbuf[(yy)&1][3];                        \
    unsigned m0 = 0, m1 = 0, m2 = 0, m3 = 0;                                  \
    float b0 = __shfl_sync(0xffffffffu, v[0][3], (lane+31)&31);               \
    float b1 = __shfl_sync(0xffffffffu, v[1][3], (lane+31)&31);               \
    float b2 = __shfl_sync(0xffffffffu, v[2][3], (lane+31)&31);               \
    float b3 = __shfl_sync(0xffffffffu, v[3][3], (lane+31)&31);               \
    float d0 = lane0 ? NEG_INF_F : b0;                                        \
    float d1 = lane0 ? b0 : b1;                                               \
    float d2 = lane0 ? b1 : b2;                                               \
    float d3 = lane0 ? b2 : b3;                                               \
    DP_Q(0, d0, r0, m0); DP_Q(1, d1, r1, m1);                                 \
    DP_Q(2, d2, r2, m2); DP_Q(3, d3, r3, m3);                                 \
    sdirs[(yy)*32 + lane] = (unsigned short)((m0 | m1) | (m2 | m3));          \
} while (0)

#define DP_BLK8(Y0) do {                                                      \
    DP_ROW4(0, (Y0)+0); DP_ROW4(1, (Y0)+1); DP_ROW4(2, (Y0)+2);               \
    DP_ROW4(3, (Y0)+3); DP_ROW4(4, (Y0)+4); DP_ROW4(5, (Y0)+5);               \
    DP_ROW4(6, (Y0)+6); DP_ROW4(7, (Y0)+7);                                   \
} while (0)

__global__ void k_dp(const float* __restrict__ text_mask,
                     const float* __restrict__ spec_mask,
                     float* __restrict__ d_out) {
    extern __shared__ unsigned char smraw[];
    unsigned short* sdirs = (unsigned short*)smraw;                     // TY*32
    int* sdur = (int*)(smraw + SM_DUR);                                 // TX
    int* sidx = (int*)(smraw + SM_IDX);                                 // TY
    float* srow0 = (float*)(smraw + SM_RING);                           // 8*512

    int b = blockIdx.x;
    int lane = threadIdx.x;
    bool lane0 = (lane == 0);
    float* srow = srow0 + lane*4;   // per-lane base within each 512-float row

    float ts = 0.f, ss = 0.f;
    for (int i = lane; i < TX_; i += 32) ts += text_mask[b*TX_ + i];
    for (int i = lane; i < TY_; i += 32) ss += spec_mask[b*TY_ + i];
    #pragma unroll
    for (int o = 16; o > 0; o >>= 1) {
        ts += __shfl_xor_sync(0xffffffffu, ts, o);
        ss += __shfl_xor_sync(0xffffffffu, ss, o);
    }
    int text_len = (int)rintf(ts);
    int spec_len = (int)rintf(ss);
    int yend8 = (spec_len + 7) & ~7;    // spec_len >= 1536 by construction

    for (int i = lane; i < TX_; i += 32) sdur[i] = 0;

    const float* base = g_negcent + (size_t)b*TY_*TX_ + lane*4;

    // prologue: stage rows 0..7 (one commit group per row)
    #pragma unroll
    for (int r = 0; r < 8; ++r) {
        const float* rp = base + (size_t)r*TX_;
        float* sd = srow + r*512;
        cp16(sd,       rp);
        cp16(sd + 128, rp + 128);
        cp16(sd + 256, rp + 256);
        cp16(sd + 384, rp + 384);
        CP_COMMIT();
    }
    CP_WAIT7();   // row 0 group complete

    float4 cbuf[2][4];
    cbuf[0][0] = *(const float4*)(srow);
    cbuf[0][1] = *(const float4*)(srow + 128);
    cbuf[0][2] = *(const float4*)(srow + 256);
    cbuf[0][3] = *(const float4*)(srow + 384);

    float v[4][4];
    #pragma unroll
    for (int q = 0; q < 4; ++q)
        #pragma unroll
        for (int j = 0; j < 4; ++j) v[q][j] = NEG_INF_F;

    // ---- phase 0: rows [0,128), Q0 only ----
    {   // row 0 special
        DP_STAGE(0, 0);
        float4 r0 = cbuf[0][0];
        if (lane0) v[0][0] = r0.x;
        sdirs[lane] = 0;
    }
    DP_ROW1(1, 1); DP_ROW1(2, 2); DP_ROW1(3, 3);
    DP_ROW1(4, 4); DP_ROW1(5, 5); DP_ROW1(6, 6); DP_ROW1(7, 7);
    for (int y0 = 8; y0 < 128; y0 += 8) {
        DP_ROW1(0, y0+0); DP_ROW1(1, y0+1); DP_ROW1(2, y0+2); DP_ROW1(3, y0+3);
        DP_ROW1(4, y0+4); DP_ROW1(5, y0+5); DP_ROW1(6, y0+6); DP_ROW1(7, y0+7);
    }

    // ---- phase 1: rows [128,256), Q0-Q1 ----
    for (int y0 = 128; y0 < 256; y0 += 8) {
        DP_ROW2(0, y0+0); DP_ROW2(1, y0+1); DP_ROW2(2, y0+2); DP_ROW2(3, y0+3);
        DP_ROW2(4, y0+4); DP_ROW2(5, y0+5); DP_ROW2(6, y0+6); DP_ROW2(7, y0+7);
    }

    // ---- phase 2: rows [256,384), Q0-Q2 ----
    for (int y0 = 256; y0 < 384; y0 += 8) {
        DP_ROW3(0, y0+0); DP_ROW3(1, y0+1); DP_ROW3(2, y0+2); DP_ROW3(3, y0+3);
        DP_ROW3(4, y0+4); DP_ROW3(5, y0+5); DP_ROW3(6, y0+6); DP_ROW3(7, y0+7);
    }

    // ---- phase 3: rows [384,1536) unconditional (spec_len >= 1536) ----
    for (int y0 = 384; y0 < 1536; y0 += 8) DP_BLK8(y0);

    // ---- phase 3 tail: 128-row chunks, constant bounds, uniform gates ----
    if (yend8 > 1536) { for (int y0 = 1536; y0 < 1664; y0 += 8) DP_BLK8(y0); }
    if (yend8 > 1664) { for (int y0 = 1664; y0 < 1792; y0 += 8) DP_BLK8(y0); }
    if (yend8 > 1792) { for (int y0 = 1792; y0 < 1920; y0 += 8) DP_BLK8(y0); }
    if (yend8 > 1920) { for (int y0 = 1920; y0 < 2048; y0 += 8) DP_BLK8(y0); }
    CP_WAIT0();
    __syncwarp();

    if (lane0) {
        // start at spec_len-1: rows above are inactive in the reference
        // (idx unchanged, path row zero) so skipping them is exact.
        int idx = text_len - 1;
        unsigned wcur = sdirs[(spec_len-1)*32 + ((idx>>2)&31)];
        for (int y = spec_len - 1; y >= 0; --y) {
            unsigned wa = 0, wb = 0;
            if (y > 0) {
                wa = sdirs[(y-1)*32 + ((idx>>2)&31)];
                int im = (idx > 0) ? idx - 1 : 0;
                wb = sdirs[(y-1)*32 + ((im>>2)&31)];
            }
            sidx[y] = idx;
            int bit = ((idx >> 7) << 2) | (idx & 3);
            bool d_at = (wcur >> bit) & 1u;
            bool move = (idx != 0) && ((idx == y) || d_at);
            if (move) { --idx; wcur = wb; }
            else      {        wcur = wa; }
        }
        g_speclen[b] = spec_len;
    }
    __syncwarp();

    for (int y = lane; y < TY_; y += 32) {
        int ix = (y < spec_len) ? sidx[y] : -1;
        g_idx[b*TY_ + y] = ix;
        if (ix >= 0) atomicAdd(&sdur[ix], 1);
    }
    __syncwarp();

    for (int i = lane; i < TX_; i += 32)
        d_out[DUR_OFF + (size_t)b*TX_ + i] = (float)sdur[i];
}

// ---------------- path one-hot ------------------------------------------------
__global__ void k_path(float* __restrict__ d_out) {
    int g = blockIdx.x * 256 + threadIdx.x;   // over B*TY*TX/4
    int x4  = (g & 127) << 2;
    int rem = g >> 7;
    int y = rem & (TY_ - 1);
    int b = rem >> 11;
    int idx = g_idx[b*TY_ + y];
    float4 o;
    o.x = (idx == x4 + 0) ? 1.f : 0.f;
    o.y = (idx == x4 + 1) ? 1.f : 0.f;
    o.z = (idx == x4 + 2) ? 1.f : 0.f;
    o.w = (idx == x4 + 3) ? 1.f : 0.f;
    ((float4*)d_out)[g] = o;
}

// ---------------- gather m_p_a / logs_p_a + fused KL partials -----------------
// exp(-2*logs_p[j]) is re-materialized from g_s (= -0.5*exp(-2*logs_p)):
// e = -2*g_s[j], bit-exact (x0.5 and x2 are exact FP scalings). No MUFU.
__global__ void k_gather(const float* __restrict__ z_p,
                         const float* __restrict__ m_p,
                         const float* __restrict__ logs_p,
                         const float* __restrict__ logs_q,
                         float* __restrict__ d_out) {
    int t = blockIdx.x * 256 + threadIdx.x;
    int c = blockIdx.y, b = blockIdx.z;
    int j = g_idx[b*TY_ + t];
    int row = b*C_ + c;
    float mv = 0.f, lv = 0.f, kl = 0.f;
    if (j >= 0) {
        mv = m_p[row*TX_ + j];
        lv = logs_p[row*TX_ + j];
        float e  = -2.0f * g_s[row*TX_ + j];   // == expf(-2*lv) exactly
        float z  = z_p[(size_t)row*TY_ + t];
        float lq = logs_q[(size_t)row*TY_ + t];
        float d  = z - mv;
        kl = lv - lq - 0.5f + 0.5f*d*d*e;
    }
    d_out[MPA_OFF + (size_t)row*TY_ + t] = mv;
    d_out[LPA_OFF + (size_t)row*TY_ + t] = lv;

    __shared__ float red[256];
    red[threadIdx.x] = kl;
    __syncthreads();
    for (int s2 = 128; s2 > 0; s2 >>= 1) {
        if (threadIdx.x < s2) red[threadIdx.x] += red[threadIdx.x + s2];
        __syncthreads();
    }
    if (threadIdx.x == 0) {
        int bid = (blockIdx.z * gridDim.y + blockIdx.y) * gridDim.x + blockIdx.x;
        g_klpart[bid] = red[0];
    }
}

// ---------------- final loss reduction (deterministic) ------------------------
__global__ void k_loss(float* __restrict__ d_out) {
    int tid = threadIdx.x;
    float p = 0.f;
    for (int i = tid; i < KL_BLOCKS; i += 256) p += g_klpart[i];
    __shared__ float red[256];
    red[tid] = p;
    __syncthreads();
    for (int s2 = 128; s2 > 0; s2 >>= 1) {
        if (tid < s2) red[tid] += red[tid + s2];
        __syncthreads();
    }
    if (tid == 0) {
        float den = 0.f;
        for (int b = 0; b < B_; ++b) den += (float)g_speclen[b];
        d_out[LOSS_OFF] = red[0] / den;
    }
}

// ---------------- launch -------------------------------------------------------
extern "C" void kernel_launch(void* const* d_in, const int* in_sizes, int n_in,
                              void* d_out, int out_size) {
    const float* z_p       = (const float*)d_in[0];
    const float* m_p       = (const float*)d_in[1];
    const float* logs_p    = (const float*)d_in[2];
    const float* logs_q    = (const float*)d_in[3];
    const float* text_mask = (const float*)d_in[4];
    const float* spec_mask = (const float*)d_in[5];
    float* out = (float*)d_out;

    k_prep_b<<<dim3(TX_/32, B_), dim3(32, 8)>>>(m_p, logs_p, spec_mask);
    k_nop<<<1, 1>>>();      // steer ncu: k_dp lands at slot 4
    k_negcent<<<dim3(TX_/BN, TY_/BM, B_), 256>>>(z_p);

    cudaFuncSetAttribute(k_dp, cudaFuncAttributeMaxDynamicSharedMemorySize, (int)DP_SMEM);
    k_dp<<<B_, 32, DP_SMEM>>>(text_mask, spec_mask, out);

    k_path<<<(int)(PATH_SZ/4/256), 256>>>(out);
    k_gather<<<dim3(TY_/256, C_, B_), 256>>>(z_p, m_p, logs_p, logs_q, out);
    k_loss<<<1, 256>>>(out);
}

// round 16
// speedup vs baseline: 1.0478x; 1.0478x over previous
#include <cuda_runtime.h>
#include <math.h>

#define B_   8
#define C_   192
#define TX_  512
#define TY_  2048
#define NEG_INF_F (-1e9f)

#define PATH_SZ ((size_t)B_*TY_*TX_)            /* 8388608 */
#define GATH_SZ ((size_t)B_*C_*TY_)             /* 3145728 */
#define MPA_OFF  (PATH_SZ)
#define LPA_OFF  (PATH_SZ + GATH_SZ)
#define LOSS_OFF (PATH_SZ + 2*GATH_SZ)
#define DUR_OFF  (LOSS_OFF + 1)

#define KL_BLOCKS (B_*C_*(TY_/256))             /* 12288 */
/* smem: dirs (TY*32 ushort) | dur (TX int) | idx (TY int) | row ring 8*512 f32 */
#define SM_DUR  ((size_t)TY_*32*2)              /* 131072 */
#define SM_IDX  (SM_DUR + TX_*4)                /* 133120 */
#define SM_RING (SM_IDX + TY_*4)                /* 141312 */
#define DP_SMEM (SM_RING + 8*512*4)             /* 157696 */

// ---------------- scratch (__device__ globals; no runtime allocation) -------
__device__ float g_s [B_*C_*TX_];               // -0.5 * exp(-2*logs_p)
__device__ float g_ms[B_*C_*TX_];               // m_p * exp(-2*logs_p)
__device__ float g_nc14[B_*TX_];                // nc1 + nc4
__device__ float g_negcent[(size_t)B_*TY_*TX_]; // rows >= spec_len stay 0 (never written)
__device__ int   g_idx[B_*TY_];                 // backtrack path index, -1 inactive
__device__ int   g_speclen[B_];                 // written by k_prep_b (pre-negcent)
__device__ float g_klpart[KL_BLOCKS];

// ---------------- packed fp32x2 helpers (sm_100+) ----------------------------
__device__ __forceinline__ unsigned long long ffma2(unsigned long long a,
                                                    unsigned long long b,
                                                    unsigned long long c) {
    unsigned long long d;
    asm("fma.rn.f32x2 %0, %1, %2, %3;" : "=l"(d) : "l"(a), "l"(b), "l"(c));
    return d;
}
__device__ __forceinline__ unsigned long long dup2(float f) {
    unsigned long long d;
    unsigned r = __float_as_uint(f);
    asm("mov.b64 %0, {%1, %1};" : "=l"(d) : "r"(r));
    return d;
}
__device__ __forceinline__ void unpk2(unsigned long long v, float& lo, float& hi) {
    unsigned a, b;
    asm("mov.b64 {%0, %1}, %2;" : "=r"(a), "=r"(b) : "l"(v));
    lo = __uint_as_float(a);
    hi = __uint_as_float(b);
}

// ---------------- cp.async helpers -------------------------------------------
__device__ __forceinline__ void cp16(const void* smem_ptr, const void* gptr) {
    unsigned sa = (unsigned)__cvta_generic_to_shared(smem_ptr);
    asm volatile("cp.async.cg.shared.global [%0], [%1], 16;" :: "r"(sa), "l"(gptr));
}
#define CP_COMMIT() asm volatile("cp.async.commit_group;")
#define CP_WAIT0()  asm volatile("cp.async.wait_group 0;")
#define CP_WAIT7()  asm volatile("cp.async.wait_group 7;")

// ---------------- profiler-steering no-op ------------------------------------
__global__ void k_nop() {}

// ---------------- prep: s' = -0.5*s, ms, nc14, spec_len ----------------------
__global__ void k_prep_b(const float* __restrict__ m_p,
                         const float* __restrict__ logs_p,
                         const float* __restrict__ spec_mask) {
    int x  = blockIdx.x * 32 + threadIdx.x;
    int b  = blockIdx.y;
    int ty = threadIdx.y;

    if (blockIdx.x == 0 && ty == 2) {
        float ss = 0.f;
        for (int i = threadIdx.x; i < TY_; i += 32) ss += spec_mask[b*TY_ + i];
        #pragma unroll
        for (int o = 16; o > 0; o >>= 1) ss += __shfl_xor_sync(0xffffffffu, ss, o);
        if (threadIdx.x == 0) g_speclen[b] = (int)rintf(ss);
    }

    float part = 0.f;
    for (int c = ty; c < C_; c += 8) {
        int off = (b*C_ + c)*TX_ + x;
        float lp = logs_p[off];
        float m  = m_p[off];
        float s  = expf(-2.f * lp);
        float ms = m * s;
        g_s[off]  = -0.5f * s;
        g_ms[off] = ms;
        part += (-0.91893853320467274178f - lp - 0.5f*m*ms);
    }
    __shared__ float red[8][32];
    red[ty][threadIdx.x] = part;
    __syncthreads();
    if (ty == 0) {
        float t = 0.f;
        #pragma unroll
        for (int r = 0; r < 8; ++r) t += red[r][threadIdx.x];
        g_nc14[b*TX_ + x] = t;
    }
}

// ---------------- neg_cent GEMM: acc += z*(z*(-0.5s) + ms) -------------------
#define BM 128
#define BN 128

__global__ void __launch_bounds__(256) k_negcent(const float* __restrict__ z_p) {
    int b  = blockIdx.z;
    int t0 = blockIdx.y * BM;
    if (t0 >= g_speclen[b]) return;   // dead rows: nothing downstream reads them

    __shared__ __align__(16) float Zs[2][8][BM];
    __shared__ __align__(16) float Ss[2][8][BN];
    __shared__ __align__(16) float Ms[2][8][BN];

    int tid = threadIdx.x;
    int tx = tid & 15, ty = tid >> 4;
    int x0 = blockIdx.x * BN;

    int lk = tid >> 5;
    int lc = (tid & 31) * 4;

    const float* zb  = z_p  + (size_t)b*C_*TY_ + t0;
    const float* sb  = g_s  + b*C_*TX_ + x0;
    const float* msb = g_ms + b*C_*TX_ + x0;

    unsigned long long acc[8][4];
    #pragma unroll
    for (int i = 0; i < 8; ++i)
        #pragma unroll
        for (int j = 0; j < 4; ++j) acc[i][j] = 0ull;

    cp16(&Zs[0][lk][lc], zb  + (size_t)lk*TY_ + lc);
    cp16(&Ss[0][lk][lc], sb  + lk*TX_ + lc);
    cp16(&Ms[0][lk][lc], msb + lk*TX_ + lc);
    CP_COMMIT();

    int buf = 0;
    for (int c0 = 0; c0 < C_; c0 += 8) {
        CP_WAIT0();
        __syncthreads();
        if (c0 + 8 < C_) {
            int nb = buf ^ 1, ck = c0 + 8;
            cp16(&Zs[nb][lk][lc], zb  + (size_t)(ck+lk)*TY_ + lc);
            cp16(&Ss[nb][lk][lc], sb  + (ck+lk)*TX_ + lc);
            cp16(&Ms[nb][lk][lc], msb + (ck+lk)*TX_ + lc);
            CP_COMMIT();
        }

        #pragma unroll
        for (int k = 0; k < 8; ++k) {
            float4 zA = *(const float4*)&Zs[buf][k][ty*8];
            float4 zB = *(const float4*)&Zs[buf][k][ty*8+4];
            unsigned long long zd[8] = {dup2(zA.x), dup2(zA.y), dup2(zA.z), dup2(zA.w),
                                        dup2(zB.x), dup2(zB.y), dup2(zB.z), dup2(zB.w)};
            ulonglong2 sA = *(const ulonglong2*)&Ss[buf][k][tx*8];
            ulonglong2 sB = *(const ulonglong2*)&Ss[buf][k][tx*8+4];
            ulonglong2 mA = *(const ulonglong2*)&Ms[buf][k][tx*8];
            ulonglong2 mB = *(const ulonglong2*)&Ms[buf][k][tx*8+4];
            unsigned long long sp[4] = {sA.x, sA.y, sB.x, sB.y};
            unsigned long long mp[4] = {mA.x, mA.y, mB.x, mB.y};

            #pragma unroll
            for (int i = 0; i < 8; ++i)
                #pragma unroll
                for (int j = 0; j < 4; ++j)
                    acc[i][j] = ffma2(zd[i], ffma2(zd[i], sp[j], mp[j]), acc[i][j]);
        }
        buf ^= 1;
    }

    int xo = x0 + tx*8;
    float4 ncA = *(const float4*)(g_nc14 + b*TX_ + xo);
    float4 ncB = *(const float4*)(g_nc14 + b*TX_ + xo + 4);
    float nc[8] = {ncA.x, ncA.y, ncA.z, ncA.w, ncB.x, ncB.y, ncB.z, ncB.w};

    #pragma unroll
    for (int i = 0; i < 8; ++i) {
        float f[8];
        #pragma unroll
        for (int j = 0; j < 4; ++j) unpk2(acc[i][j], f[2*j], f[2*j+1]);
        int t = t0 + ty*8 + i;
        float* o0 = g_negcent + ((size_t)b*TY_ + t)*TX_ + xo;
        float4 w;
        w.x = f[0]+nc[0]; w.y = f[1]+nc[1]; w.z = f[2]+nc[2]; w.w = f[3]+nc[3];
        *(float4*)o0 = w;
        w.x = f[4]+nc[4]; w.y = f[5]+nc[5]; w.z = f[6]+nc[6]; w.w = f[7]+nc[7];
        *(float4*)(o0+4) = w;
    }
}

// ---------------- MAS forward DP + backtrack (R14-exact dp codegen) -----------
// Lane L owns x = q*128 + L*4 + j  (q=0..3, j=0..3).
// Dirs mask bit for x: lane=(x>>2)&31, bit=((x>>7)<<2)|(x&3).
// Row y's data is in registers cbuf[y&1], LDS'd from smem during row y-1.
// Smem ring depth 8, one cp.async commit group per row; at the tail we commit
// DUMMY reloads of row TY-1 so exactly 8 groups stay in flight and wait_group 7
// always GUARANTEES row y+1's group completion (deterministic, clock-independent).
// ALL inner-loop bounds compile-time (R8 lesson). Single mm OR-chain (R15 lesson:
// splitting it reshuffled the schedule and regressed).

#define DP_Q(Q, DB, RQ) do {                                                  \
    float sc0 = RQ.x, sc1 = RQ.y, sc2 = RQ.z, sc3 = RQ.w;                     \
    { bool p = v[Q][2] > v[Q][3]; if (p) mm |= (1u << (Q*4+3));               \
      v[Q][3] = sc3 + (p ? v[Q][2] : v[Q][3]); }                              \
    { bool p = v[Q][1] > v[Q][2]; if (p) mm |= (1u << (Q*4+2));               \
      v[Q][2] = sc2 + (p ? v[Q][1] : v[Q][2]); }                              \
    { bool p = v[Q][0] > v[Q][1]; if (p) mm |= (1u << (Q*4+1));               \
      v[Q][1] = sc1 + (p ? v[Q][0] : v[Q][1]); }                              \
    { bool p = (DB) > v[Q][0];    if (p) mm |= (1u << (Q*4+0));               \
      v[Q][0] = sc0 + (p ? (DB) : v[Q][0]); }                                 \
} while (0)

/* stage: commit row yy+8 (dummy=row TY-1 at tail), wait, LDS row yy+1 -> regs */
#define DP_STAGE(SLOT, yy) do {                                               \
    const float* rp = base +                                                  \
        (size_t)(((yy)+8 < TY_) ? (yy)+8 : TY_-1)*TX_;                        \
    float* sd = srow + (SLOT)*512;                                            \
    cp16(sd,       rp);                                                       \
    cp16(sd + 128, rp + 128);                                                 \
    cp16(sd + 256, rp + 256);                                                 \
    cp16(sd + 384, rp + 384);                                                 \
    CP_COMMIT();                                                              \
    CP_WAIT7();                                                               \
    { const float* sl = srow + ((((yy)+1)&7))*512;                            \
      float4* nb = cbuf[((yy)+1)&1];                                          \
      nb[0] = *(const float4*)(sl);                                           \
      nb[1] = *(const float4*)(sl + 128);                                     \
      nb[2] = *(const float4*)(sl + 256);                                     \
      nb[3] = *(const float4*)(sl + 384); }                                   \
} while (0)

#define DP_ROW1(SLOT, yy) do {                                                \
    DP_STAGE(SLOT, yy);                                                       \
    float4 r0 = cbuf[(yy)&1][0];                                              \
    unsigned mm = 0;                                                          \
    float b0 = __shfl_sync(0xffffffffu, v[0][3], (lane+31)&31);               \
    float d0 = lane0 ? NEG_INF_F : b0;                                        \
    DP_Q(0, d0, r0);                                                          \
    sdirs[(yy)*32 + lane] = (unsigned short)mm;                               \
} while (0)

#define DP_ROW2(SLOT, yy) do {                                                \
    DP_STAGE(SLOT, yy);                                                       \
    float4 r0 = cbuf[(yy)&1][0], r1 = cbuf[(yy)&1][1];                        \
    unsigned mm = 0;                                                          \
    float b0 = __shfl_sync(0xffffffffu, v[0][3], (lane+31)&31);               \
    float b1 = __shfl_sync(0xffffffffu, v[1][3], (lane+31)&31);               \
    float d0 = lane0 ? NEG_INF_F : b0;                                        \
    float d1 = lane0 ? b0 : b1;                                               \
    DP_Q(0, d0, r0); DP_Q(1, d1, r1);                                         \
    sdirs[(yy)*32 + lane] = (unsigned short)mm;                               \
} while (0)

#define DP_ROW3(SLOT, yy) do {                                                \
    DP_STAGE(SLOT, yy);                                                       \
    float4 r0 = cbuf[(yy)&1][0], r1 = cbuf[(yy)&1][1], r2 = cbuf[(yy)&1][2];  \
    unsigned mm = 0;                                                          \
    float b0 = __shfl_sync(0xffffffffu, v[0][3], (lane+31)&31);               \
    float b1 = __shfl_sync(0xffffffffu, v[1][3], (lane+31)&31);               \
    float b2 = __shfl_sync(0xffffffffu, v[2][3], (lane+31)&31);               \
    float d0 = lane0 ? NEG_INF_F : b0;                                        \
    float d1 = lane0 ? b0 : b1;                                               \
    float d2 = lane0 ? b1 : b2;                                               \
    DP_Q(0, d0, r0); DP_Q(1, d1, r1); DP_Q(2, d2, r2);                        \
    sdirs[(yy)*32 + lane] = (unsigned short)mm;                               \
} while (0)

#define DP_ROW4(SLOT, yy) do {                                                \
    DP_STAGE(SLOT, yy);                                                       \
    float4 r0 = cbuf[(yy)&1][0], r1 = cbuf[(yy)&1][1];                        \
    float4 r2 = cbuf[(yy)&1][2], r3 = cbuf[(yy)&1][3];                        \
    unsigned mm = 0;                                                          \
    float b0 = __shfl_sync(0xffffffffu, v[0][3], (lane+31)&31);               \
    float b1 = __shfl_sync(0xffffffffu, v[1][3], (lane+31)&31);               \
    float b2 = __shfl_sync(0xffffffffu, v[2][3], (lane+31)&31);               \
    float b3 = __shfl_sync(0xffffffffu, v[3][3], (lane+31)&31);               \
    float d0 = lane0 ? NEG_INF_F : b0;                                        \
    float d1 = lane0 ? b0 : b1;                                               \
    float d2 = lane0 ? b1 : b2;                                               \
    float d3 = lane0 ? b2 : b3;                                               \
    DP_Q(0, d0, r0); DP_Q(1, d1, r1); DP_Q(2, d2, r2); DP_Q(3, d3, r3);       \
    sdirs[(yy)*32 + lane] = (unsigned short)mm;                               \
} while (0)

#define DP_BLK8(Y0) do {                                                      \
    DP_ROW4(0, (Y0)+0); DP_ROW4(1, (Y0)+1); DP_ROW4(2, (Y0)+2);               \
    DP_ROW4(3, (Y0)+3); DP_ROW4(4, (Y0)+4); DP_ROW4(5, (Y0)+5);               \
    DP_ROW4(6, (Y0)+6); DP_ROW4(7, (Y0)+7);                                   \
} while (0)

__global__ void k_dp(const float* __restrict__ text_mask,
                     const float* __restrict__ spec_mask,
                     float* __restrict__ d_out) {
    extern __shared__ unsigned char smraw[];
    unsigned short* sdirs = (unsigned short*)smraw;                     // TY*32
    int* sdur = (int*)(smraw + SM_DUR);                                 // TX
    int* sidx = (int*)(smraw + SM_IDX);                                 // TY
    float* srow0 = (float*)(smraw + SM_RING);                           // 8*512

    int b = blockIdx.x;
    int lane = threadIdx.x;
    bool lane0 = (lane == 0);
    float* srow = srow0 + lane*4;   // per-lane base within each 512-float row

    float ts = 0.f, ss = 0.f;
    for (int i = lane; i < TX_; i += 32) ts += text_mask[b*TX_ + i];
    for (int i = lane; i < TY_; i += 32) ss += spec_mask[b*TY_ + i];
    #pragma unroll
    for (int o = 16; o > 0; o >>= 1) {
        ts += __shfl_xor_sync(0xffffffffu, ts, o);
        ss += __shfl_xor_sync(0xffffffffu, ss, o);
    }
    int text_len = (int)rintf(ts);
    int spec_len = (int)rintf(ss);
    int yend8 = (spec_len + 7) & ~7;    // spec_len >= 1536 by construction

    for (int i = lane; i < TX_; i += 32) sdur[i] = 0;

    const float* base = g_negcent + (size_t)b*TY_*TX_ + lane*4;

    // prologue: stage rows 0..7 (one commit group per row)
    #pragma unroll
    for (int r = 0; r < 8; ++r) {
        const float* rp = base + (size_t)r*TX_;
        float* sd = srow + r*512;
        cp16(sd,       rp);
        cp16(sd + 128, rp + 128);
        cp16(sd + 256, rp + 256);
        cp16(sd + 384, rp + 384);
        CP_COMMIT();
    }
    CP_WAIT7();   // row 0 group complete

    float4 cbuf[2][4];
    cbuf[0][0] = *(const float4*)(srow);
    cbuf[0][1] = *(const float4*)(srow + 128);
    cbuf[0][2] = *(const float4*)(srow + 256);
    cbuf[0][3] = *(const float4*)(srow + 384);

    float v[4][4];
    #pragma unroll
    for (int q = 0; q < 4; ++q)
        #pragma unroll
        for (int j = 0; j < 4; ++j) v[q][j] = NEG_INF_F;

    // ---- phase 0: rows [0,128), Q0 only ----
    {   // row 0 special
        DP_STAGE(0, 0);
        float4 r0 = cbuf[0][0];
        if (lane0) v[0][0] = r0.x;
        sdirs[lane] = 0;
    }
    DP_ROW1(1, 1); DP_ROW1(2, 2); DP_ROW1(3, 3);
    DP_ROW1(4, 4); DP_ROW1(5, 5); DP_ROW1(6, 6); DP_ROW1(7, 7);
    for (int y0 = 8; y0 < 128; y0 += 8) {
        DP_ROW1(0, y0+0); DP_ROW1(1, y0+1); DP_ROW1(2, y0+2); DP_ROW1(3, y0+3);
        DP_ROW1(4, y0+4); DP_ROW1(5, y0+5); DP_ROW1(6, y0+6); DP_ROW1(7, y0+7);
    }

    // ---- phase 1: rows [128,256), Q0-Q1 ----
    for (int y0 = 128; y0 < 256; y0 += 8) {
        DP_ROW2(0, y0+0); DP_ROW2(1, y0+1); DP_ROW2(2, y0+2); DP_ROW2(3, y0+3);
        DP_ROW2(4, y0+4); DP_ROW2(5, y0+5); DP_ROW2(6, y0+6); DP_ROW2(7, y0+7);
    }

    // ---- phase 2: rows [256,384), Q0-Q2 ----
    for (int y0 = 256; y0 < 384; y0 += 8) {
        DP_ROW3(0, y0+0); DP_ROW3(1, y0+1); DP_ROW3(2, y0+2); DP_ROW3(3, y0+3);
        DP_ROW3(4, y0+4); DP_ROW3(5, y0+5); DP_ROW3(6, y0+6); DP_ROW3(7, y0+7);
    }

    // ---- phase 3: rows [384,1536) unconditional (spec_len >= 1536) ----
    for (int y0 = 384; y0 < 1536; y0 += 8) DP_BLK8(y0);

    // ---- phase 3 tail: 128-row chunks, constant bounds, uniform gates ----
    if (yend8 > 1536) { for (int y0 = 1536; y0 < 1664; y0 += 8) DP_BLK8(y0); }
    if (yend8 > 1664) { for (int y0 = 1664; y0 < 1792; y0 += 8) DP_BLK8(y0); }
    if (yend8 > 1792) { for (int y0 = 1792; y0 < 1920; y0 += 8) DP_BLK8(y0); }
    if (yend8 > 1920) { for (int y0 = 1920; y0 < 2048; y0 += 8) DP_BLK8(y0); }
    CP_WAIT0();
    __syncwarp();

    if (lane0) {
        int idx = text_len - 1;
        unsigned wcur = sdirs[(TY_-1)*32 + ((idx>>2)&31)];
        for (int y = TY_ - 1; y >= 0; --y) {
            unsigned wa = 0, wb = 0;
            if (y > 0) {
                wa = sdirs[(y-1)*32 + ((idx>>2)&31)];
                int im = (idx > 0) ? idx - 1 : 0;
                wb = sdirs[(y-1)*32 + ((im>>2)&31)];
            }
            bool active = y < spec_len;
            sidx[y] = active ? idx : -1;
            int bit = ((idx >> 7) << 2) | (idx & 3);
            bool d_at = (wcur >> bit) & 1u;
            bool move = (idx != 0) && ((idx == y) || d_at);
            if (active && move) { --idx; wcur = wb; }
            else                {        wcur = wa; }
        }
        g_speclen[b] = spec_len;
    }
    __syncwarp();

    for (int y = lane; y < TY_; y += 32) {
        int ix = sidx[y];
        g_idx[b*TY_ + y] = ix;
        if (ix >= 0) atomicAdd(&sdur[ix], 1);
    }
    __syncwarp();

    for (int i = lane; i < TX_; i += 32)
        d_out[DUR_OFF + (size_t)b*TX_ + i] = (float)sdur[i];
}

// ---------------- path one-hot ------------------------------------------------
__global__ void k_path(float* __restrict__ d_out) {
    int g = blockIdx.x * 256 + threadIdx.x;   // over B*TY*TX/4
    int x4  = (g & 127) << 2;
    int rem = g >> 7;
    int y = rem & (TY_ - 1);
    int b = rem >> 11;
    int idx = g_idx[b*TY_ + y];
    float4 o;
    o.x = (idx == x4 + 0) ? 1.f : 0.f;
    o.y = (idx == x4 + 1) ? 1.f : 0.f;
    o.z = (idx == x4 + 2) ? 1.f : 0.f;
    o.w = (idx == x4 + 3) ? 1.f : 0.f;
    ((float4*)d_out)[g] = o;
}

// ---------------- gather m_p_a / logs_p_a + fused KL partials -----------------
// exp(-2*logs_p[j]) re-materialized from g_s (= -0.5*exp(-2*logs_p)):
// e = -2*g_s[j], bit-exact (x0.5 and x2 are exact FP scalings). No MUFU.
__global__ void k_gather(const float* __restrict__ z_p,
                         const float* __restrict__ m_p,
                         const float* __restrict__ logs_p,
                         const float* __restrict__ logs_q,
                         float* __restrict__ d_out) {
    int t = blockIdx.x * 256 + threadIdx.x;
    int c = blockIdx.y, b = blockIdx.z;
    int j = g_idx[b*TY_ + t];
    int row = b*C_ + c;
    float mv = 0.f, lv = 0.f, kl = 0.f;
    if (j >= 0) {
        mv = m_p[row*TX_ + j];
        lv = logs_p[row*TX_ + j];
        float e  = -2.0f * g_s[row*TX_ + j];   // == expf(-2*lv) exactly
        float z  = z_p[(size_t)row*TY_ + t];
        float lq = logs_q[(size_t)row*TY_ + t];
        float d  = z - mv;
        kl = lv - lq - 0.5f + 0.5f*d*d*e;
    }
    d_out[MPA_OFF + (size_t)row*TY_ + t] = mv;
    d_out[LPA_OFF + (size_t)row*TY_ + t] = lv;

    __shared__ float red[256];
    red[threadIdx.x] = kl;
    __syncthreads();
    for (int s2 = 128; s2 > 0; s2 >>= 1) {
        if (threadIdx.x < s2) red[threadIdx.x] += red[threadIdx.x + s2];
        __syncthreads();
    }
    if (threadIdx.x == 0) {
        int bid = (blockIdx.z * gridDim.y + blockIdx.y) * gridDim.x + blockIdx.x;
        g_klpart[bid] = red[0];
    }
}

// ---------------- final loss reduction (deterministic) ------------------------
__global__ void k_loss(float* __restrict__ d_out) {
    int tid = threadIdx.x;
    float p = 0.f;
    for (int i = tid; i < KL_BLOCKS; i += 256) p += g_klpart[i];
    __shared__ float red[256];
    red[tid] = p;
    __syncthreads();
    for (int s2 = 128; s2 > 0; s2 >>= 1) {
        if (tid < s2) red[tid] += red[tid + s2];
        __syncthreads();
    }
    if (tid == 0) {
        float den = 0.f;
        for (int b = 0; b < B_; ++b) den += (float)g_speclen[b];
        d_out[LOSS_OFF] = red[0] / den;
    }
}

// ---------------- launch -------------------------------------------------------
extern "C" void kernel_launch(void* const* d_in, const int* in_sizes, int n_in,
                              void* d_out, int out_size) {
    const float* z_p       = (const float*)d_in[0];
    const float* m_p       = (const float*)d_in[1];
    const float* logs_p    = (const float*)d_in[2];
    const float* logs_q    = (const float*)d_in[3];
    const float* text_mask = (const float*)d_in[4];
    const float* spec_mask = (const float*)d_in[5];
    float* out = (float*)d_out;

    k_prep_b<<<dim3(TX_/32, B_), dim3(32, 8)>>>(m_p, logs_p, spec_mask);
    k_nop<<<1, 1>>>();      // steer ncu: k_dp lands at slot 4
    k_negcent<<<dim3(TX_/BN, TY_/BM, B_), 256>>>(z_p);

    cudaFuncSetAttribute(k_dp, cudaFuncAttributeMaxDynamicSharedMemorySize, (int)DP_SMEM);
    k_dp<<<B_, 32, DP_SMEM>>>(text_mask, spec_mask, out);

    k_path<<<(int)(PATH_SZ/4/256), 256>>>(out);
    k_gather<<<dim3(TY_/256, C_, B_), 256>>>(z_p, m_p, logs_p, logs_q, out);
    k_loss<<<1, 256>>>(out);
}